// round 1
// baseline (speedup 1.0000x reference)
#include <cuda_runtime.h>

// FIR bandpass, zero-phase, reflect_limited padding.
// out[t] = sum_{k=0}^{412} h[k] * xv[t + 206 - k]
// xv[m] = x[m]                   for 0 <= m < T
//       = 2*x[0]   - x[-m]       for m < 0
//       = 2*x[T-1] - x[2T-2-m]   for m >= T

#define T_LEN    30000
#define N_TAPS   413
#define HALF     206        // (N_TAPS-1)/2
#define TILE     3000       // outputs per block; 10 * 3000 = 30000 exactly
#define NTILES   10
#define NTHREADS 384
#define RPT      8          // outputs per thread (384*8 = 3072 >= 3000)
#define H_PAD    416        // taps padded to multiple of 8 (zeros)
// logical smem x range: j in [-8, 3484)  (3072 + 412 window reach + guard)
#define J_MAX    3484
#define SX_PHYS  3928       // sidx(3483)+1

// padded shared index: +1 word every 8 words -> lane stride 9 -> conflict-free
__device__ __forceinline__ int sidx(int j) {
    int t = j + 8;              // shift so j >= -8 is valid
    return t + (t >> 3);
}

__global__ __launch_bounds__(NTHREADS)
void fir_bandpass_kernel(const float* __restrict__ x,
                         const float* __restrict__ h,
                         float* __restrict__ out) {
    __shared__ float sx[SX_PHYS];
    __shared__ __align__(16) float sh[H_PAD];

    const int row  = blockIdx.y;               // 0..2047  (b*64 + c)
    const int tile = blockIdx.x;               // 0..9
    const int s    = tile * TILE;              // tile start in t
    const int tid  = threadIdx.x;

    const float* __restrict__ xr  = x   + (size_t)row * T_LEN;
    float* __restrict__       outr = out + (size_t)row * T_LEN;

    // ---- load extended tile into smem (reflect_limited applied here) ----
    const float x0 = xr[0];
    const float xl = xr[T_LEN - 1];
    for (int idx = tid; idx < J_MAX + 8; idx += NTHREADS) {
        const int j = idx - 8;                  // logical j in [-8, 3484)
        const int m = s - HALF + j;             // global sample index
        float v;
        if (m < 0)            v = 2.0f * x0 - xr[-m];
        else if (m >= T_LEN)  v = 2.0f * xl - xr[2 * T_LEN - 2 - m];
        else                  v = xr[m];
        sx[sidx(j)] = v;
    }
    for (int idx = tid; idx < H_PAD; idx += NTHREADS)
        sh[idx] = (idx < N_TAPS) ? h[idx] : 0.0f;
    __syncthreads();

    // ---- per-thread state ----
    // thread outputs: t = s + 8*tid + r, r = 0..7
    // window start (local idx) at tap k: j0 = jq - k, jq = 8*tid + 412 (== 4 mod 8)
    const int jq = RPT * tid + 2 * HALF;

    float acc[RPT];
#pragma unroll
    for (int r = 0; r < RPT; ++r) acc[r] = 0.0f;

    // circular window: w[j & 7] holds xv_local[j] for j in [j0, j0+7]
    float w[8];
    const float* p = &sx[sidx(jq)];
    // initial fill (j0 == 4 mod 8): phys offsets for d=0..7 are 0,1,2,3,5,6,7,8
    w[4] = p[0]; w[5] = p[1]; w[6] = p[2]; w[7] = p[3];
    w[0] = p[5]; w[1] = p[6]; w[2] = p[7]; w[3] = p[8];

    for (int k = 0; k < H_PAD; k += 8) {
        const float4 ha = *reinterpret_cast<const float4*>(&sh[k]);
        const float4 hb = *reinterpret_cast<const float4*>(&sh[k + 4]);
        const float hv[8] = {ha.x, ha.y, ha.z, ha.w, hb.x, hb.y, hb.z, hb.w};
        // phys offsets for new elements j0-1..j0-8 (j0 == 4 mod 8):
        constexpr int ld_off[8] = {-1, -2, -3, -4, -6, -7, -8, -9};
#pragma unroll
        for (int i = 0; i < 8; ++i) {
            const float hk = hv[i];
#pragma unroll
            for (int r = 0; r < RPT; ++r)
                acc[r] = fmaf(w[(4 - i + r) & 7], hk, acc[r]);
            // slide window down by one: load xv_local[j0-1-i] into slot (3-i)&7
            w[(3 - i) & 7] = p[ld_off[i]];
        }
        p -= 9;   // phys step for j0 -= 8
    }

    // ---- store (float4 x2, coalesced); ghost threads (8*tid >= TILE) drop out
    if (RPT * tid < TILE) {
        const int t0 = s + RPT * tid;
        float4 o0 = make_float4(acc[0], acc[1], acc[2], acc[3]);
        float4 o1 = make_float4(acc[4], acc[5], acc[6], acc[7]);
        *reinterpret_cast<float4*>(&outr[t0])     = o0;
        *reinterpret_cast<float4*>(&outr[t0 + 4]) = o1;
    }
}

extern "C" void kernel_launch(void* const* d_in, const int* in_sizes, int n_in,
                              void* d_out, int out_size) {
    const float* x = (const float*)d_in[0];   // (32, 64, 30000) f32
    const float* h = (const float*)d_in[1];   // (413,) f32
    float* out = (float*)d_out;

    dim3 grid(NTILES, 32 * 64);
    fir_bandpass_kernel<<<grid, NTHREADS>>>(x, h, out);
}